// round 15
// baseline (speedup 1.0000x reference)
#include <cuda_runtime.h>

// Problem constants
#define BATCH 4
#define T 32
#define NTOK (BATCH * T)      // 128
#define C 512
#define ENC 32
#define DIM 1024

// Scratch (no allocations allowed): device globals
__device__ float  d_e[NTOK][32];       // unit encodings (K1 -> K2)
__device__ float2 d_P[NTOK][4][32];    // AoS (fallback path only)
__device__ float2 d_Q[NTOK][4][32];    // AoS (fallback path only)

__device__ __forceinline__ float2 cmul(float2 a, float2 b) {
    return make_float2(a.x * b.x - a.y * b.y, a.x * b.y + a.y * b.x);
}

// packed f32x2 helpers (sm_103a)
__device__ __forceinline__ unsigned long long pack2(float lo, float hi) {
    unsigned long long r;
    asm("mov.b64 %0, {%1, %2};" : "=l"(r) : "f"(lo), "f"(hi));
    return r;
}
__device__ __forceinline__ void unpack2(unsigned long long v, float& lo, float& hi) {
    asm("mov.b64 {%0, %1}, %2;" : "=f"(lo), "=f"(hi) : "l"(v));
}
__device__ __forceinline__ unsigned long long fma2(unsigned long long a,
                                                   unsigned long long b,
                                                   unsigned long long c) {
    unsigned long long d;
    asm("fma.rn.f32x2 %0, %1, %2, %3;" : "=l"(d) : "l"(a), "l"(b), "l"(c));
    return d;
}

// ---------------------------------------------------------------------------
// Kernel 1 (tiny): e[tok] = normalize(x[tok] @ W^T + b).  grid=128, block=128.
// ---------------------------------------------------------------------------
__global__ void __launch_bounds__(128)
enc_kernel(const float* __restrict__ x,
           const float* __restrict__ W,
           const float* __restrict__ bias) {
    __shared__ float partial[4][32];
    int tok = blockIdx.x;
    int tid = threadIdx.x;           // 128
    int k = tid & 31, p = tid >> 5;  // p 0..3, 128 c each

    const float4* wr4 = (const float4*)(W + (size_t)k * C + p * 128);
    const float4* xc4 = (const float4*)(x + (size_t)tok * C + p * 128);
    float s0 = 0.f, s1 = 0.f, s2 = 0.f, s3 = 0.f;
#pragma unroll
    for (int cc = 0; cc < 32; cc++) {
        float4 wv = wr4[cc];
        float4 xv = xc4[cc];
        s0 += wv.x * xv.x; s1 += wv.y * xv.y;
        s2 += wv.z * xv.z; s3 += wv.w * xv.w;
    }
    partial[p][k] = (s0 + s1) + (s2 + s3);
    __syncthreads();

    if (tid < 32) {
        float v = partial[0][tid] + partial[1][tid] + partial[2][tid] +
                  partial[3][tid] + bias[tid];
        float sq = v * v;
#pragma unroll
        for (int o = 16; o; o >>= 1) sq += __shfl_xor_sync(0xffffffffu, sq, o);
        d_e[tok][tid] = v * rsqrtf(sq);
    }
}

// ---------------------------------------------------------------------------
// Kernel 2 (fused circuit + expand). grid=128 (block per token (b,i)),
// block=512. Recomputes the cheap circuit parts per block (no P/Q globals):
//   Ga = kron(RY0*RX0) wires 0..4, Gb wires 5..9; G2a/G2b = kron(RY1) split
//   by column parity: G2?p[p][r][t] = G2?[r][(t<<1)|p].
//   u = Ga*e(i);  v_j = Gb*e(j) for all 32 j of batch b.
//   P_k[r] = sum_mm G2ap[pa][r][mm ^ 8*(k&1)] * u[m^(m>>1)],   m=(mm<<1)|pa
//   Q_k[r](j) = sum_mm G2bp[pb][r][mm] * v_j[(m^(m>>1))^xb],   m=(mm<<1)|pb
//   (pa=k>>1, pb=k&1, xb=(k>>1)<<4)
// Then rank-4 real expansion from smem (R13 inner loop):
//   out[(tok*32+j)*1024 + a*32 + b0] = sum_k Px*Qx - Py*Qy
// ---------------------------------------------------------------------------
__global__ void __launch_bounds__(512)
circuit_expand_kernel(const float* __restrict__ th_rx0,
                      const float* __restrict__ th_ry0,
                      const float* __restrict__ th_ry1,
                      float* __restrict__ out) {
    __shared__ __align__(16) union U {
        struct { float2 Ga[32][32]; float2 Gb[32][32]; } A;      // 16KB
        struct { float Qx[32][4][32]; float Qy[32][4][32]; } B;  // 32KB
    } u_;
    __shared__ __align__(16) float G2ap[2][32][16];   // parity-split, 4KB
    __shared__ __align__(16) float G2bp[2][32][16];   // 4KB
    __shared__ __align__(16) float es[32][32];        // batch encodings, 4KB
    __shared__ float2 vs[32][32];                     // v per batch token, 8KB
    __shared__ float2 usm[32];                        // u (own token)
    __shared__ float2 Psm[4][32];
    __shared__ float2 M1w[10][2][2];
    __shared__ float  M2w[10][2][2];

    int tok = blockIdx.x;            // b*32 + i
    int b = tok >> 5, i = tok & 31;
    int tid = threadIdx.x;           // 512

    // Stage batch encodings (written by K1): 1024 floats = 256 float4
    if (tid < 256)
        ((float4*)&es[0][0])[tid] = ((const float4*)&d_e[b << 5][0])[tid];

    if (tid < 10) {
        float crx = cosf(th_rx0[tid] * 0.5f), srx = sinf(th_rx0[tid] * 0.5f);
        float cry = cosf(th_ry0[tid] * 0.5f), sry = sinf(th_ry0[tid] * 0.5f);
        M1w[tid][0][0] = make_float2( cry * crx,  sry * srx);
        M1w[tid][0][1] = make_float2(-sry * crx, -cry * srx);
        M1w[tid][1][0] = make_float2( sry * crx, -cry * srx);
        M1w[tid][1][1] = make_float2( cry * crx, -sry * srx);
        float c1 = cosf(th_ry1[tid] * 0.5f), s1 = sinf(th_ry1[tid] * 0.5f);
        M2w[tid][0][0] =  c1; M2w[tid][0][1] = -s1;
        M2w[tid][1][0] =  s1; M2w[tid][1][1] =  c1;
    }
    __syncthreads();

    // Kronecker factors (2 cells per thread)
    for (int cell = tid; cell < 1024; cell += 512) {
        int r = cell >> 5, c = cell & 31;
        float2 ga = make_float2(1.f, 0.f), gb = make_float2(1.f, 0.f);
        float g2a = 1.f, g2b = 1.f;
#pragma unroll
        for (int j = 0; j < 5; j++) {
            int rb = (r >> (4 - j)) & 1;
            int cb = (c >> (4 - j)) & 1;
            ga  = cmul(ga, M1w[j][rb][cb]);
            gb  = cmul(gb, M1w[5 + j][rb][cb]);
            g2a *= M2w[j][rb][cb];
            g2b *= M2w[5 + j][rb][cb];
        }
        u_.A.Ga[r][c] = ga; u_.A.Gb[r][c] = gb;
        G2ap[c & 1][r][c >> 1] = g2a;
        G2bp[c & 1][r][c >> 1] = g2b;
    }
    __syncthreads();

    // vs[j][r], vs[j][r+1]: thread -> (j = tid>>4, r = (tid&15)*2)
    {
        int j = tid >> 4;
        int r = (tid & 15) << 1;
        float er[32];
#pragma unroll
        for (int n = 0; n < 8; n++) {
            float4 ev = ((const float4*)&es[j][0])[n];
            er[4*n] = ev.x; er[4*n+1] = ev.y; er[4*n+2] = ev.z; er[4*n+3] = ev.w;
        }
        float re0 = 0.f, im0 = 0.f, re1 = 0.f, im1 = 0.f;
#pragma unroll
        for (int c = 0; c < 32; c++) {
            float2 g0 = u_.A.Gb[r][c];
            float2 g1 = u_.A.Gb[r + 1][c];
            re0 += g0.x * er[c]; im0 += g0.y * er[c];
            re1 += g1.x * er[c]; im1 += g1.y * er[c];
        }
        vs[j][r]     = make_float2(re0, im0);
        vs[j][r + 1] = make_float2(re1, im1);
    }
    // u for own token (threads 0..31)
    if (tid < 32) {
        int r = tid;
        float re = 0.f, im = 0.f;
#pragma unroll
        for (int c = 0; c < 32; c++) {
            float2 g = u_.A.Ga[r][c];
            float ev = es[i][c];
            re += g.x * ev; im += g.y * ev;
        }
        usm[r] = make_float2(re, im);
    }
    __syncthreads();   // last reads of Ga/Gb; union B writes may begin

    // P (threads 0..127): Psm[k][rr]
    if (tid < 128) {
        int k4 = tid >> 5, rr = tid & 31;
        int pa = k4 >> 1;
        int f8 = (k4 & 1) << 3;
        float re = 0.f, im = 0.f;
#pragma unroll
        for (int mm = 0; mm < 16; mm++) {
            int m = (mm << 1) | pa;
            float2 uu = usm[m ^ (m >> 1)];
            float g = G2ap[pa][rr][mm ^ f8];
            re += g * uu.x; im += g * uu.y;
        }
        Psm[k4][rr] = make_float2(re, im);
    }
    // Q for all batch tokens -> smem SoA. thread -> (j=tid>>4, k4=(tid>>2)&3,
    // rr in [(tid&3)*8, +8)).
    {
        int j  = tid >> 4;
        int k4 = (tid >> 2) & 3;
        int rb = (tid & 3) << 3;
        int pb = k4 & 1, xb = (k4 >> 1) << 4;
        float2 vv[16];
#pragma unroll
        for (int mm = 0; mm < 16; mm++) {
            int m = (mm << 1) | pb;
            vv[mm] = vs[j][(m ^ (m >> 1)) ^ xb];
        }
#pragma unroll
        for (int n = 0; n < 8; n++) {
            int rr = rb + n;
            const float4* g4 = (const float4*)&G2bp[pb][rr][0];
            float re = 0.f, im = 0.f;
#pragma unroll
            for (int q = 0; q < 4; q++) {
                float4 g = g4[q];
                re += g.x * vv[4*q].x   + g.y * vv[4*q+1].x
                    + g.z * vv[4*q+2].x + g.w * vv[4*q+3].x;
                im += g.x * vv[4*q].y   + g.y * vv[4*q+1].y
                    + g.z * vv[4*q+2].y + g.w * vv[4*q+3].y;
            }
            u_.B.Qx[j][k4][rr] = re;
            u_.B.Qy[j][k4][rr] = im;
        }
    }
    __syncthreads();

    // Expand (R13 inner loop): 8 j-lanes x 64 patch threads, 4 j-iterations.
    int lane = tid >> 6;             // 0..7
    int t4 = tid & 63;
    int a_base = (t4 >> 3) << 2;     // 0,4,...,28
    int b0 = (t4 & 7) << 2;          // 0,4,...,28

    unsigned long long pxx[4][4], pyn[4][4];
#pragma unroll
    for (int k = 0; k < 4; k++)
#pragma unroll
        for (int da = 0; da < 4; da++) {
            float2 Pv = Psm[k][a_base + da];
            pxx[da][k] = pack2(Pv.x, Pv.x);
            pyn[da][k] = pack2(-Pv.y, -Pv.y);
        }

    float* obase = out + ((size_t)tok << 15);   // tok*32*1024
#pragma unroll
    for (int jo = 0; jo < 4; jo++) {
        int j = (jo << 3) | lane;
        unsigned long long qxL[4], qxH[4], qyL[4], qyH[4];
#pragma unroll
        for (int k = 0; k < 4; k++) {
            float4 fx = *(const float4*)&u_.B.Qx[j][k][b0];
            qxL[k] = pack2(fx.x, fx.y); qxH[k] = pack2(fx.z, fx.w);
            float4 fy = *(const float4*)&u_.B.Qy[j][k][b0];
            qyL[k] = pack2(fy.x, fy.y); qyH[k] = pack2(fy.z, fy.w);
        }
        float* oj = obase + ((size_t)j << 10);
#pragma unroll
        for (int da = 0; da < 4; da++) {
            unsigned long long accL = 0ull, accH = 0ull;   // (0.0f,0.0f)
#pragma unroll
            for (int k = 0; k < 4; k++) {
                accL = fma2(pxx[da][k], qxL[k], accL);
                accL = fma2(pyn[da][k], qyL[k], accL);
                accH = fma2(pxx[da][k], qxH[k], accH);
                accH = fma2(pyn[da][k], qyH[k], accH);
            }
            float r0, r1, r2, r3;
            unpack2(accL, r0, r1);
            unpack2(accH, r2, r3);
            *(float4*)&oj[(a_base + da) * 32 + b0] = make_float4(r0, r1, r2, r3);
        }
    }
}

// ---------------------------------------------------------------------------
// Fallback path (out_size != 4194304): previous two-kernel complex pipeline.
// ---------------------------------------------------------------------------
__global__ void __launch_bounds__(256)
enc_pq_fallback(const float* __restrict__ x,
                const float* __restrict__ W,
                const float* __restrict__ bias,
                const float* __restrict__ th_rx0,
                const float* __restrict__ th_ry0,
                const float* __restrict__ th_ry1) {
    __shared__ float2 M1w[10][2][2];
    __shared__ float  M2w[10][2][2];
    __shared__ float2 Ga[32][32], Gb[32][32];
    __shared__ float  G2a[32][32], G2b[32][32];
    __shared__ float  partial[8][32];
    __shared__ float  e[32];
    __shared__ float2 us[32], vs[32];

    int tok = blockIdx.x;
    int tid = threadIdx.x;  // 256

    if (tid < 10) {
        float crx = cosf(th_rx0[tid] * 0.5f), srx = sinf(th_rx0[tid] * 0.5f);
        float cry = cosf(th_ry0[tid] * 0.5f), sry = sinf(th_ry0[tid] * 0.5f);
        M1w[tid][0][0] = make_float2( cry * crx,  sry * srx);
        M1w[tid][0][1] = make_float2(-sry * crx, -cry * srx);
        M1w[tid][1][0] = make_float2( sry * crx, -cry * srx);
        M1w[tid][1][1] = make_float2( cry * crx, -sry * srx);
        float c1 = cosf(th_ry1[tid] * 0.5f), s1 = sinf(th_ry1[tid] * 0.5f);
        M2w[tid][0][0] =  c1; M2w[tid][0][1] = -s1;
        M2w[tid][1][0] =  s1; M2w[tid][1][1] =  c1;
    }
    __syncthreads();

    for (int cell = tid; cell < 1024; cell += 256) {
        int r = cell >> 5, c = cell & 31;
        float2 ga = make_float2(1.f, 0.f), gb = make_float2(1.f, 0.f);
        float g2a = 1.f, g2b = 1.f;
#pragma unroll
        for (int j = 0; j < 5; j++) {
            int rb = (r >> (4 - j)) & 1;
            int cb = (c >> (4 - j)) & 1;
            ga  = cmul(ga, M1w[j][rb][cb]);
            gb  = cmul(gb, M1w[5 + j][rb][cb]);
            g2a *= M2w[j][rb][cb];
            g2b *= M2w[5 + j][rb][cb];
        }
        Ga[r][c] = ga; Gb[r][c] = gb; G2a[r][c] = g2a; G2b[r][c] = g2b;
    }

    {
        int k = tid & 31, p = tid >> 5;
        const float4* wr4 = (const float4*)(W + (size_t)k * C + p * 64);
        const float4* xc4 = (const float4*)(x + (size_t)tok * C + p * 64);
        float s = 0.f;
#pragma unroll
        for (int cc = 0; cc < 16; cc++) {
            float4 wv = wr4[cc];
            float4 xv = xc4[cc];
            s += wv.x * xv.x + wv.y * xv.y + wv.z * xv.z + wv.w * xv.w;
        }
        partial[p][k] = s;
    }
    __syncthreads();

    if (tid < 32) {
        float v = bias[tid];
#pragma unroll
        for (int p = 0; p < 8; p++) v += partial[p][tid];
        float sq = v * v;
#pragma unroll
        for (int o = 16; o; o >>= 1) sq += __shfl_xor_sync(0xffffffffu, sq, o);
        e[tid] = v * rsqrtf(sq);
    }
    __syncthreads();

    if (tid < 64) {
        int r = tid & 31, side = tid >> 5;
        float re = 0.f, im = 0.f;
#pragma unroll
        for (int c = 0; c < 32; c++) {
            float ev = e[c];
            float2 m = side ? Gb[r][c] : Ga[r][c];
            re += m.x * ev; im += m.y * ev;
        }
        if (side) vs[r] = make_float2(re, im);
        else      us[r] = make_float2(re, im);
    }
    __syncthreads();

    {
        int o = tid;
        int which = o >> 7;
        int k4 = (o >> 5) & 3;
        int rr = o & 31;
        float re = 0.f, im = 0.f;
        if (which == 0) {
            int pa = k4 >> 1, fa = (k4 & 1) << 4;
#pragma unroll
            for (int mm = 0; mm < 16; mm++) {
                int m = (mm << 1) | pa;
                float2 uu = us[m ^ (m >> 1)];
                float g = G2a[rr][m ^ fa];
                re += g * uu.x; im += g * uu.y;
            }
            d_P[tok][k4][rr] = make_float2(re, im);
        } else {
            int pb = k4 & 1, xb = (k4 >> 1) << 4;
#pragma unroll
            for (int mm = 0; mm < 16; mm++) {
                int m = (mm << 1) | pb;
                float2 vv = vs[(m ^ (m >> 1)) ^ xb];
                float g = G2b[rr][m];
                re += g * vv.x; im += g * vv.y;
            }
            d_Q[tok][k4][rr] = make_float2(re, im);
        }
    }
}

__global__ void __launch_bounds__(512)
expand_cplx_kernel(float4* __restrict__ out, long long nf4_limit) {
    int blk = blockIdx.x;          // b*1024 + i*32 + j
    int b = blk >> 10;
    int i = (blk >> 5) & 31;
    int j = blk & 31;

    __shared__ float2 Ps[4][32];
    __shared__ float2 Qs[4][32];

    int tid = threadIdx.x;  // 512
    if (tid < 128) {
        Ps[tid >> 5][tid & 31] = d_P[b * T + i][tid >> 5][tid & 31];
    } else if (tid < 256) {
        int t = tid - 128;
        Qs[t >> 5][t & 31] = d_Q[b * T + j][t >> 5][t & 31];
    }
    __syncthreads();

    int e0 = tid * 2;
    int a  = e0 >> 5;
    int b0 = e0 & 31;

    unsigned long long acc0 = 0ull, acc1 = 0ull;
#pragma unroll
    for (int k = 0; k < 4; k++) {
        float2 P  = Ps[k][a];
        float2 Q0 = Qs[k][b0];
        float2 Q1 = Qs[k][b0 + 1];
        unsigned long long pxx = pack2(P.x, P.x);
        unsigned long long pyn = pack2(-P.y, P.y);
        acc0 = fma2(pxx, pack2(Q0.x, Q0.y), acc0);
        acc0 = fma2(pyn, pack2(Q0.y, Q0.x), acc0);
        acc1 = fma2(pxx, pack2(Q1.x, Q1.y), acc1);
        acc1 = fma2(pyn, pack2(Q1.y, Q1.x), acc1);
    }
    float re0, im0, re1, im1;
    unpack2(acc0, re0, im0);
    unpack2(acc1, re1, im1);

    long long idx = (long long)blk * 512 + tid;
    if (idx < nf4_limit)
        out[idx] = make_float4(re0, im0, re1, im1);
}

// ---------------------------------------------------------------------------
extern "C" void kernel_launch(void* const* d_in, const int* in_sizes, int n_in,
                              void* d_out, int out_size) {
    // Resolve inputs by element count (order-independent):
    //   x: 65536 (B*T*C), W_tok: 16384 (ENC*C), b_tok: 32 (ENC),
    //   thetas: three size-10 arrays, relative order rx0, ry0, ry1.
    const float* x = nullptr;
    const float* W = nullptr;
    const float* bvec = nullptr;
    const float* th[3] = {nullptr, nullptr, nullptr};
    int nth = 0;
    for (int i = 0; i < n_in; i++) {
        int sz = in_sizes[i];
        const float* p = (const float*)d_in[i];
        if (sz == BATCH * T * C)      x = p;
        else if (sz == ENC * C)       W = p;
        else if (sz == ENC)           bvec = p;
        else if (sz == 10 && nth < 3) th[nth++] = p;
    }
    if (!x || !W || !bvec || nth != 3) return;

    if (out_size == 4194304) {
        // Live path: tiny enc kernel + fused circuit/expand kernel.
        enc_kernel<<<NTOK, 128>>>(x, W, bvec);
        circuit_expand_kernel<<<NTOK, 512>>>(th[0], th[1], th[2],
                                             (float*)d_out);
    } else {
        // Fallback: interleaved complex pairs.
        enc_pq_fallback<<<NTOK, 256>>>(x, W, bvec, th[0], th[1], th[2]);
        long long nfloats = (long long)out_size;
        if (nfloats > 8388608LL) nfloats = 8388608LL;
        long long nf4 = nfloats / 4;
        if (nf4 > 2097152LL) nf4 = 2097152LL;
        expand_cplx_kernel<<<BATCH * T * T, 512>>>((float4*)d_out, nf4);
    }
}

// round 17
// speedup vs baseline: 2.0915x; 2.0915x over previous
#include <cuda_runtime.h>

// Problem constants
#define BATCH 4
#define T 32
#define NTOK (BATCH * T)      // 128
#define C 512
#define ENC 32
#define DIM 1024

// Scratch (no allocations allowed): device globals
__device__ float2 d_P[NTOK][4][32];
__device__ float2 d_Q[NTOK][4][32];

__device__ __forceinline__ float2 cmul(float2 a, float2 b) {
    return make_float2(a.x * b.x - a.y * b.y, a.x * b.y + a.y * b.x);
}

// packed f32x2 helpers (sm_103a)
__device__ __forceinline__ unsigned long long pack2(float lo, float hi) {
    unsigned long long r;
    asm("mov.b64 %0, {%1, %2};" : "=l"(r) : "f"(lo), "f"(hi));
    return r;
}
__device__ __forceinline__ void unpack2(unsigned long long v, float& lo, float& hi) {
    asm("mov.b64 {%0, %1}, %2;" : "=f"(lo), "=f"(hi) : "l"(v));
}
__device__ __forceinline__ unsigned long long fma2(unsigned long long a,
                                                   unsigned long long b,
                                                   unsigned long long c) {
    unsigned long long d;
    asm("fma.rn.f32x2 %0, %1, %2, %3;" : "=l"(d) : "l"(a), "l"(b), "l"(c));
    return d;
}

// ---------------------------------------------------------------------------
// Kernel 1 (fused): per token:
//   enc = normalize(x @ W^T + b); u = Ga*enc, v = Gb*enc;
//   P_k[r] = sum_{m:m&1==pa} G2a[r][m^fa] * u[m ^ (m>>1)]
//   Q_k[r] = sum_{m:m&1==pb} G2b[r][m]  * v[(m ^ (m>>1)) ^ xb]
// (Ga = kron(RY0*RX0) wires 0..4, Gb wires 5..9, G2a/G2b = kron(RY1);
//  sigma_inv(m) = m ^ (m>>1); pa=k>>1, fa=(k&1)<<4, pb=k&1, xb=(k>>1)<<4.)
// Smem arrays PADDED to 33 columns: kills the 16/32-way bank conflicts in
// the u/v phase (lanes differ in r for Ga/Gb) and the P/Q phase (lanes
// differ in rr for G2a/G2b).
// grid = 128 (one block per token), block = 128 threads.
// ---------------------------------------------------------------------------
__global__ void __launch_bounds__(128)
enc_pq_kernel(const float* __restrict__ x,
              const float* __restrict__ W,
              const float* __restrict__ bias,
              const float* __restrict__ th_rx0,
              const float* __restrict__ th_ry0,
              const float* __restrict__ th_ry1) {
    __shared__ float2 M1w[10][2][2];  // layer-1 combined RY*RX per wire
    __shared__ float  M2w[10][2][2];  // layer-2 RY per wire (real)
    __shared__ float2 Ga[32][33], Gb[32][33];   // padded: 2-way max
    __shared__ float  G2a[32][33], G2b[32][33]; // padded: conflict-free
    __shared__ float  partial[4][32];
    __shared__ float  e[32];
    __shared__ float2 us[32], vs[32];

    int tok = blockIdx.x;
    int tid = threadIdx.x;  // 128

    if (tid < 10) {
        float crx = cosf(th_rx0[tid] * 0.5f), srx = sinf(th_rx0[tid] * 0.5f);
        float cry = cosf(th_ry0[tid] * 0.5f), sry = sinf(th_ry0[tid] * 0.5f);
        // M = RY * RX
        M1w[tid][0][0] = make_float2( cry * crx,  sry * srx);
        M1w[tid][0][1] = make_float2(-sry * crx, -cry * srx);
        M1w[tid][1][0] = make_float2( sry * crx, -cry * srx);
        M1w[tid][1][1] = make_float2( cry * crx, -sry * srx);
        float c1 = cosf(th_ry1[tid] * 0.5f), s1 = sinf(th_ry1[tid] * 0.5f);
        M2w[tid][0][0] =  c1; M2w[tid][0][1] = -s1;
        M2w[tid][1][0] =  s1; M2w[tid][1][1] =  c1;
    }
    __syncthreads();

    // Build the four 32x32 Kronecker factors (8 cells per thread)
    for (int cell = tid; cell < 1024; cell += 128) {
        int r = cell >> 5, c = cell & 31;
        float2 ga = make_float2(1.f, 0.f), gb = make_float2(1.f, 0.f);
        float g2a = 1.f, g2b = 1.f;
#pragma unroll
        for (int j = 0; j < 5; j++) {
            int rb = (r >> (4 - j)) & 1;
            int cb = (c >> (4 - j)) & 1;
            ga  = cmul(ga, M1w[j][rb][cb]);
            gb  = cmul(gb, M1w[5 + j][rb][cb]);
            g2a *= M2w[j][rb][cb];
            g2b *= M2w[5 + j][rb][cb];
        }
        Ga[r][c] = ga; Gb[r][c] = gb; G2a[r][c] = g2a; G2b[r][c] = g2b;
    }

    // GEMV partials: thread (p,k) sums 128 c-elements of row k (float4 loads)
    {
        int k = tid & 31, p = tid >> 5;
        const float4* wr4 = (const float4*)(W + (size_t)k * C + p * 128);
        const float4* xc4 = (const float4*)(x + (size_t)tok * C + p * 128);
        float s = 0.f;
#pragma unroll
        for (int cc = 0; cc < 32; cc++) {
            float4 wv = wr4[cc];
            float4 xv = xc4[cc];
            s += wv.x * xv.x + wv.y * xv.y + wv.z * xv.z + wv.w * xv.w;
        }
        partial[p][k] = s;
    }
    __syncthreads();

    if (tid < 32) {
        float v = partial[0][tid] + partial[1][tid] + partial[2][tid] +
                  partial[3][tid] + bias[tid];
        float sq = v * v;
#pragma unroll
        for (int o = 16; o; o >>= 1) sq += __shfl_xor_sync(0xffffffffu, sq, o);
        e[tid] = v * rsqrtf(sq);
    }
    __syncthreads();

    // u = Ga * e, v = Gb * e  (threads 0..63)
    if (tid < 64) {
        int r = tid & 31, side = tid >> 5;
        float re = 0.f, im = 0.f;
#pragma unroll
        for (int c = 0; c < 32; c++) {
            float ev = e[c];
            float2 m = side ? Gb[r][c] : Ga[r][c];
            re += m.x * ev; im += m.y * ev;
        }
        if (side) vs[r] = make_float2(re, im);
        else      us[r] = make_float2(re, im);
    }
    __syncthreads();

    // P/Q: 256 complex outputs (4 P-vectors + 4 Q-vectors of 32), 2 per thread
#pragma unroll
    for (int pass = 0; pass < 2; pass++) {
        int o = tid + pass * 128;
        int which = o >> 7;             // 0 -> P, 1 -> Q
        int k4 = (o >> 5) & 3;
        int rr = o & 31;
        float re = 0.f, im = 0.f;
        if (which == 0) {
            int pa = k4 >> 1, fa = (k4 & 1) << 4;
#pragma unroll
            for (int mm = 0; mm < 16; mm++) {
                int m = (mm << 1) | pa;
                float2 uu = us[m ^ (m >> 1)];
                float g = G2a[rr][m ^ fa];
                re += g * uu.x; im += g * uu.y;
            }
            d_P[tok][k4][rr] = make_float2(re, im);
        } else {
            int pb = k4 & 1, xb = (k4 >> 1) << 4;
#pragma unroll
            for (int mm = 0; mm < 16; mm++) {
                int m = (mm << 1) | pb;
                float2 vv = vs[(m ^ (m >> 1)) ^ xb];
                float g = G2b[rr][m];
                re += g * vv.x; im += g * vv.y;
            }
            d_Q[tok][k4][rr] = make_float2(re, im);
        }
    }
}

// ---------------------------------------------------------------------------
// Kernel 2: rank-4 expansion, REAL parts (R8 champion structure).
// One block per (b,i); block stages all Q of batch b in SoA smem once, then
// loops over j. Thread owns a 4a x 4b0 patch: P packed in regs outside the
// j-loop, per-j only 8 LDS.128 (Q) + 32 fma2 + 4 STG.128.
//   out[(b*1024 + i*32 + j)*1024 + a*32 + b0] = sum_k Px*Qx - Py*Qy
// grid = 128, block = 256 (4 j-lanes x 64 patch-threads).
// ---------------------------------------------------------------------------
__global__ void __launch_bounds__(256)
expand_real2_kernel(float* __restrict__ out) {
    int blk = blockIdx.x;       // b*32 + i
    int b = blk >> 5, i = blk & 31;

    __shared__ float  Qx[32][4][32];   // [j][k][b0]
    __shared__ float  Qy[32][4][32];
    __shared__ float2 Psm[4][32];      // [k][a]

    int t = threadIdx.x;  // 256

    // Stage all Q of batch b: 4096 float2, flat index n = j*128 + k*32 + b0
    {
        const float2* qsrc = &d_Q[b * T][0][0];
        float* qx = &Qx[0][0][0];
        float* qy = &Qy[0][0][0];
#pragma unroll
        for (int n = 0; n < 16; n++) {
            int idx = t + n * 256;
            float2 v = qsrc[idx];
            qx[idx] = v.x;
            qy[idx] = v.y;
        }
    }
    if (t < 128) {
        Psm[t >> 5][t & 31] = d_P[b * T + i][t >> 5][t & 31];
    }
    __syncthreads();

    int jj = t >> 6;            // 0..3: which j within each group of 4
    int t4 = t & 63;
    int a_base = (t4 >> 3) << 2;   // 0,4,...,28
    int b0 = (t4 & 7) << 2;        // 0,4,...,28

    // Pack P into registers: (P.x,P.x) and (-P.y,-P.y) per (da,k)
    unsigned long long pxx[4][4], pyn[4][4];
#pragma unroll
    for (int da = 0; da < 4; da++)
#pragma unroll
        for (int k = 0; k < 4; k++) {
            float2 P = Psm[k][a_base + da];
            pxx[da][k] = pack2(P.x, P.x);
            pyn[da][k] = pack2(-P.y, -P.y);
        }

    float* obase = out + (((size_t)b * 1024 + (size_t)i * 32) << 10);

#pragma unroll
    for (int jo = 0; jo < 8; jo++) {
        int j = (jo << 2) | jj;
        // Q pairs for this j: per k one LDS.128 from Qx and one from Qy
        ulonglong2 qxv[4], qyv[4];
#pragma unroll
        for (int k = 0; k < 4; k++) {
            qxv[k] = *(const ulonglong2*)&Qx[j][k][b0];
            qyv[k] = *(const ulonglong2*)&Qy[j][k][b0];
        }
        float* oj = obase + ((size_t)j << 10);
#pragma unroll
        for (int da = 0; da < 4; da++) {
            unsigned long long accL = 0ull, accH = 0ull;  // (0.0f,0.0f)
#pragma unroll
            for (int k = 0; k < 4; k++) {
                accL = fma2(pxx[da][k], qxv[k].x, accL);
                accL = fma2(pyn[da][k], qyv[k].x, accL);
                accH = fma2(pxx[da][k], qxv[k].y, accH);
                accH = fma2(pyn[da][k], qyv[k].y, accH);
            }
            float r0, r1, r2, r3;
            unpack2(accL, r0, r1);
            unpack2(accH, r2, r3);
            *(float4*)&oj[(a_base + da) * 32 + b0] = make_float4(r0, r1, r2, r3);
        }
    }
}

// ---------------------------------------------------------------------------
// Kernel 2b: interleaved complex64 fallback (not the live path).
// ---------------------------------------------------------------------------
__global__ void __launch_bounds__(512)
expand_cplx_kernel(float4* __restrict__ out, long long nf4_limit) {
    int blk = blockIdx.x;          // b*1024 + i*32 + j
    int b = blk >> 10;
    int i = (blk >> 5) & 31;
    int j = blk & 31;

    __shared__ float2 Ps[4][32];
    __shared__ float2 Qs[4][32];

    int tid = threadIdx.x;  // 512
    if (tid < 128) {
        Ps[tid >> 5][tid & 31] = d_P[b * T + i][tid >> 5][tid & 31];
    } else if (tid < 256) {
        int t = tid - 128;
        Qs[t >> 5][t & 31] = d_Q[b * T + j][t >> 5][t & 31];
    }
    __syncthreads();

    int e0 = tid * 2;
    int a  = e0 >> 5;
    int b0 = e0 & 31;

    unsigned long long acc0 = 0ull, acc1 = 0ull;
#pragma unroll
    for (int k = 0; k < 4; k++) {
        float2 P  = Ps[k][a];
        float2 Q0 = Qs[k][b0];
        float2 Q1 = Qs[k][b0 + 1];
        unsigned long long pxx = pack2(P.x, P.x);
        unsigned long long pyn = pack2(-P.y, P.y);
        acc0 = fma2(pxx, pack2(Q0.x, Q0.y), acc0);
        acc0 = fma2(pyn, pack2(Q0.y, Q0.x), acc0);
        acc1 = fma2(pxx, pack2(Q1.x, Q1.y), acc1);
        acc1 = fma2(pyn, pack2(Q1.y, Q1.x), acc1);
    }
    float re0, im0, re1, im1;
    unpack2(acc0, re0, im0);
    unpack2(acc1, re1, im1);

    long long idx = (long long)blk * 512 + tid;
    if (idx < nf4_limit)
        out[idx] = make_float4(re0, im0, re1, im1);
}

// ---------------------------------------------------------------------------
extern "C" void kernel_launch(void* const* d_in, const int* in_sizes, int n_in,
                              void* d_out, int out_size) {
    // Resolve inputs by element count (order-independent):
    //   x: 65536 (B*T*C), W_tok: 16384 (ENC*C), b_tok: 32 (ENC),
    //   thetas: three size-10 arrays, relative order rx0, ry0, ry1.
    const float* x = nullptr;
    const float* W = nullptr;
    const float* bvec = nullptr;
    const float* th[3] = {nullptr, nullptr, nullptr};
    int nth = 0;
    for (int i = 0; i < n_in; i++) {
        int sz = in_sizes[i];
        const float* p = (const float*)d_in[i];
        if (sz == BATCH * T * C)      x = p;
        else if (sz == ENC * C)       W = p;
        else if (sz == ENC)           bvec = p;
        else if (sz == 10 && nth < 3) th[nth++] = p;
    }
    if (!x || !W || !bvec || nth != 3) return;

    enc_pq_kernel<<<NTOK, 128>>>(x, W, bvec, th[0], th[1], th[2]);

    if (out_size == 4194304) {
        // Live path: float32 output, 4M elements (16MB): real parts only.
        expand_real2_kernel<<<NTOK, 256>>>((float*)d_out);
    } else {
        // Fallback: interleaved complex pairs.
        long long nfloats = (long long)out_size;
        if (nfloats > 8388608LL) nfloats = 8388608LL;
        long long nf4 = nfloats / 4;
        if (nf4 > 2097152LL) nf4 = 2097152LL;
        expand_cplx_kernel<<<BATCH * T * T, 512>>>((float4*)d_out, nf4);
    }
}